// round 1
// baseline (speedup 1.0000x reference)
#include <cuda_runtime.h>
#include <math.h>

#define TOKENS 65536
#define DIN 512
#define HDIM 256
#define BM 128
#define KC 16
#define AS_STRIDE 132   // 128 + 4 pad (keeps float4 alignment)
#define BS_STRIDE 260   // 256 + 4 pad
#define NTHREADS 512

// ---------------- device scratch (allocation-free) ----------------
__device__ int g_vcount;
__device__ int g_pcount;
__device__ int g_vidx[TOKENS];
__device__ int g_pidx[TOKENS];
__device__ int g_is64;

// ---------------- kernel 0: reset counters + dtype sniff ----------------
// agent_type_ids may be int32 (JAX x64 disabled) or int64. Values are 0..3,
// so if dtype is int64 every odd 32-bit word is 0. Probability of a false
// positive with random int32 data in {0..3} over 128 samples is 4^-128.
__global__ void reset_kernel(const int* __restrict__ ids32) {
    int nz = 0;
    #pragma unroll 8
    for (int i = 1; i < 256; i += 2) nz |= ids32[i];
    g_is64 = (nz == 0) ? 1 : 0;
    g_vcount = 0;
    g_pcount = 0;
}

// ---------------- kernel 1: classify, zero logits, write masks ----------------
// mask_mode: 0 = no masks in d_out, 1 = float 0/1 masks, 2 = packed byte masks
__global__ void classify_kernel(const int* __restrict__ ids32,
                                float* __restrict__ out, int mask_mode) {
    int t = blockIdx.x * blockDim.x + threadIdx.x;
    if (t >= TOKENS) return;
    int is64 = g_is64;
    int type = is64 ? ids32[2 * t] : ids32[t];
    bool vm = (type == 1);
    bool pm = (type == 2);

    // zero the full logits row; GEMM overwrites v/p rows (ped only cols 0..1)
    float* row = out + (size_t)t * 6;
    #pragma unroll
    for (int o = 0; o < 6; o++) row[o] = 0.0f;

    if (mask_mode == 1) {
        out[TOKENS * 6 + t]          = vm ? 1.0f : 0.0f;
        out[TOKENS * 6 + TOKENS + t] = pm ? 1.0f : 0.0f;
    } else if (mask_mode == 2) {
        unsigned char* m = (unsigned char*)(out + TOKENS * 6);
        m[t]          = vm ? 1 : 0;
        m[TOKENS + t] = pm ? 1 : 0;
    }

    int lane = threadIdx.x & 31;
    // warp-aggregated append to vehicle list
    unsigned vb = __ballot_sync(0xffffffffu, vm);
    if (vm) {
        int leader = __ffs(vb) - 1;
        int base = 0;
        if (lane == leader) base = atomicAdd(&g_vcount, __popc(vb));
        base = __shfl_sync(vb, base, leader);
        g_vidx[base + __popc(vb & ((1u << lane) - 1u))] = t;
    }
    // warp-aggregated append to pedestrian list
    unsigned pb = __ballot_sync(0xffffffffu, pm);
    if (pm) {
        int leader = __ffs(pb) - 1;
        int base = 0;
        if (lane == leader) base = atomicAdd(&g_pcount, __popc(pb));
        base = __shfl_sync(pb, base, leader);
        g_pidx[base + __popc(pb & ((1u << lane) - 1u))] = t;
    }
}

// ---------------- kernel 2: fused gathered MLP (per head) ----------------
__device__ __forceinline__ float gelu_exact(float x) {
    return 0.5f * x * (1.0f + erff(x * 0.7071067811865476f));
}

__global__ __launch_bounds__(NTHREADS, 1)
void mlp_kernel(const float* __restrict__ repr3,
                const float* __restrict__ vW1, const float* __restrict__ vB1,
                const float* __restrict__ vW2, const float* __restrict__ vB2,
                const float* __restrict__ pW1, const float* __restrict__ pB1,
                const float* __restrict__ pW2, const float* __restrict__ pB2,
                float* __restrict__ out)
{
    const int head = blockIdx.z;
    const int count = head ? g_pcount : g_vcount;
    const int tile  = blockIdx.x;
    if (tile * BM >= count) return;

    const int*   list = head ? g_pidx : g_vidx;
    const float* W1   = head ? pW1 : vW1;
    const float* B1   = head ? pB1 : vB1;
    const float* W2   = head ? pW2 : vW2;
    const float* B2   = head ? pB2 : vB2;
    const int    ODIM = head ? 2 : 6;

    __shared__ float As[KC][AS_STRIDE];
    __shared__ float Bs[KC][BS_STRIDE];
    __shared__ float sW2[6][HDIM];
    __shared__ float sB1[HDIM];
    __shared__ float sB2[6];
    __shared__ int   sTok[BM];

    const int tid = threadIdx.x;

    // stage constants
    for (int i = tid; i < ODIM * HDIM; i += NTHREADS) sW2[i / HDIM][i % HDIM] = W2[i];
    for (int i = tid; i < HDIM; i += NTHREADS) sB1[i] = B1[i];
    if (tid < ODIM) sB2[tid] = B2[tid];
    if (tid < BM) {
        int m = tile * BM + tid;
        sTok[tid] = (m < count) ? list[m] : list[0];
    }
    __syncthreads();

    const int tx = tid & 31;   // N direction (H cols)
    const int ty = tid >> 5;   // M direction (tokens)
    const int n0 = tx * 4;
    const int m0 = ty * 4;

    float c[8][8];
    #pragma unroll
    for (int i = 0; i < 8; i++)
        #pragma unroll
        for (int j = 0; j < 8; j++) c[i][j] = 0.0f;

    // A-load mapping: one float4 per thread per chunk
    const int ai = tid >> 2;          // token slot 0..127
    const int ak = (tid & 3) * 4;     // k offset within chunk
    const float* aptr = repr3 + (size_t)sTok[ai] * DIN + ak;

    // B-load mapping: two float4 per thread per chunk
    const int bn = tid >> 1;          // W1 row (H col) 0..255
    const int bk = (tid & 1) * 8;     // k offset within chunk
    const float* bptr = W1 + (size_t)bn * DIN + bk;

    for (int kt = 0; kt < DIN; kt += KC) {
        float4 av = *(const float4*)(aptr + kt);
        float4 b0 = *(const float4*)(bptr + kt);
        float4 b1v = *(const float4*)(bptr + kt + 4);

        As[ak + 0][ai] = av.x;  As[ak + 1][ai] = av.y;
        As[ak + 2][ai] = av.z;  As[ak + 3][ai] = av.w;

        Bs[bk + 0][bn] = b0.x;  Bs[bk + 1][bn] = b0.y;
        Bs[bk + 2][bn] = b0.z;  Bs[bk + 3][bn] = b0.w;
        Bs[bk + 4][bn] = b1v.x; Bs[bk + 5][bn] = b1v.y;
        Bs[bk + 6][bn] = b1v.z; Bs[bk + 7][bn] = b1v.w;
        __syncthreads();

        #pragma unroll
        for (int k = 0; k < KC; k++) {
            float4 a0 = *(const float4*)&As[k][m0];
            float4 a1 = *(const float4*)&As[k][m0 + 64];
            float4 w0 = *(const float4*)&Bs[k][n0];
            float4 w1 = *(const float4*)&Bs[k][n0 + 128];
            float a[8] = {a0.x, a0.y, a0.z, a0.w, a1.x, a1.y, a1.z, a1.w};
            float b[8] = {w0.x, w0.y, w0.z, w0.w, w1.x, w1.y, w1.z, w1.w};
            #pragma unroll
            for (int i = 0; i < 8; i++)
                #pragma unroll
                for (int j = 0; j < 8; j++)
                    c[i][j] = fmaf(a[i], b[j], c[i][j]);
        }
        __syncthreads();
    }

    // bias + exact GELU in registers
    #pragma unroll
    for (int i = 0; i < 8; i++) {
        #pragma unroll
        for (int j = 0; j < 8; j++) {
            int ncol = (j < 4) ? (n0 + j) : (n0 + 128 + (j - 4));
            c[i][j] = gelu_exact(c[i][j] + sB1[ncol]);
        }
    }

    // second layer (H -> ODIM) via warp-shuffle reduction across tx lanes
    for (int o = 0; o < ODIM; o++) {
        float w[8];
        #pragma unroll
        for (int j = 0; j < 8; j++) {
            int ncol = (j < 4) ? (n0 + j) : (n0 + 128 + (j - 4));
            w[j] = sW2[o][ncol];
        }
        #pragma unroll
        for (int i = 0; i < 8; i++) {
            float p = 0.0f;
            #pragma unroll
            for (int j = 0; j < 8; j++) p = fmaf(c[i][j], w[j], p);
            #pragma unroll
            for (int s = 16; s > 0; s >>= 1)
                p += __shfl_xor_sync(0xffffffffu, p, s);
            if (tx == 0) {
                int m = (i < 4) ? (m0 + i) : (m0 + 64 + (i - 4));
                if (tile * BM + m < count) {
                    out[(size_t)sTok[m] * 6 + o] = p + sB2[o];
                }
            }
        }
    }
}

// ---------------- launch ----------------
extern "C" void kernel_launch(void* const* d_in, const int* in_sizes, int n_in,
                              void* d_out, int out_size) {
    const float* repr3 = (const float*)d_in[0];
    const int*   ids   = (const int*)d_in[1];   // int32 or int64; sniffed on device
    const float* vW1 = (const float*)d_in[2];
    const float* vb1 = (const float*)d_in[3];
    const float* vW2 = (const float*)d_in[4];
    const float* vb2 = (const float*)d_in[5];
    const float* pW1 = (const float*)d_in[6];
    const float* pb1 = (const float*)d_in[7];
    const float* pW2 = (const float*)d_in[8];
    const float* pb2 = (const float*)d_in[9];
    float* out = (float*)d_out;

    // infer output layout from element count:
    //   393216            -> logits only
    //   393216+2*65536    -> logits + two float mask arrays
    //   393216+32768      -> logits + two packed byte mask arrays
    int mask_mode = 0;
    if (out_size >= TOKENS * 6 + 2 * TOKENS)      mask_mode = 1;
    else if (out_size >= TOKENS * 6 + TOKENS / 2) mask_mode = 2;

    reset_kernel<<<1, 1>>>(ids);
    classify_kernel<<<TOKENS / 256, 256>>>(ids, out, mask_mode);

    dim3 grid(TOKENS / BM, 1, 2);   // max tiles per head; blocks early-exit past count
    mlp_kernel<<<grid, NTHREADS>>>(repr3, vW1, vb1, vW2, vb2,
                                   pW1, pb1, pW2, pb2, out);
}

// round 3
// speedup vs baseline: 2.3187x; 2.3187x over previous
#include <cuda_runtime.h>
#include <cuda_bf16.h>
#include <math.h>
#include <stdint.h>

#define TOKENS 65536
#define DIN 512
#define HDIM 256
#define BM 128            // tokens per CTA tile
#define KC 32             // fp32 K elements per chunk
#define NCHUNK 16         // 512/32
#define NT 512            // threads per CTA
#define ROWB 80           // padded smem row bytes (32 bf16 = 64B + 16B pad)

// ---- dynamic SMEM layout (bytes) ----
#define A_OFF    0
#define A_SPLIT  10240    // 128 rows * 80
#define A_STAGE  20480    // hi + lo
#define B_OFF    40960
#define B_SPLIT  20480    // 256 rows * 80
#define B_STAGE  40960
#define TOK_OFF  122880   // int[128]
#define W2_OFF   123392   // float[6*256]
#define B1_OFF   129536   // float[256]
#define B2_OFF   130560   // float[8]
#define RED_OFF  130592   // float[4][128][6] = 12288
#define SMEM_TOTAL 142880

// ---------------- device globals (allocation-free scratch) ----------------
__device__ int g_vcount, g_pcount;
__device__ int g_vidx[TOKENS];
__device__ int g_pidx[TOKENS];
// prepacked W1, both heads: [head][chunk][hi 16KB | lo 16KB] (rows of 64B)
__device__ __align__(16) unsigned char g_wpack[2 * NCHUNK * 32768];

// ---------------- PTX helpers ----------------
__device__ __forceinline__ uint32_t smem_u32(const void* p) {
    uint32_t a;
    asm("{ .reg .u64 t; cvta.to.shared.u64 t, %1; cvt.u32.u64 %0, t; }" : "=r"(a) : "l"(p));
    return a;
}
__device__ __forceinline__ void cp_async16(uint32_t dst, const void* src) {
    asm volatile("cp.async.ca.shared.global [%0], [%1], 16;" :: "r"(dst), "l"(src) : "memory");
}
#define CP_COMMIT() asm volatile("cp.async.commit_group;" ::: "memory")
#define CP_WAIT0()  asm volatile("cp.async.wait_group 0;" ::: "memory")

__device__ __forceinline__ void ldm4(uint32_t (&r)[4], uint32_t addr) {
    asm volatile("ldmatrix.sync.aligned.m8n8.x4.shared.b16 {%0,%1,%2,%3}, [%4];"
        : "=r"(r[0]), "=r"(r[1]), "=r"(r[2]), "=r"(r[3]) : "r"(addr));
}
__device__ __forceinline__ void mma16816(float (&d)[4], const uint32_t (&a)[4],
                                         uint32_t b0, uint32_t b1) {
    asm volatile(
        "mma.sync.aligned.m16n8k16.row.col.f32.bf16.bf16.f32 "
        "{%0,%1,%2,%3},{%4,%5,%6,%7},{%8,%9},{%0,%1,%2,%3};"
        : "+f"(d[0]), "+f"(d[1]), "+f"(d[2]), "+f"(d[3])
        : "r"(a[0]), "r"(a[1]), "r"(a[2]), "r"(a[3]), "r"(b0), "r"(b1));
}

__device__ __forceinline__ void split_bf16(float x, uint16_t& h, uint16_t& l) {
    __nv_bfloat16 hb = __float2bfloat16_rn(x);
    __nv_bfloat16 lb = __float2bfloat16_rn(x - __bfloat162float(hb));
    h = __bfloat16_as_ushort(hb);
    l = __bfloat16_as_ushort(lb);
}

// ---------------- kernel: prepack W1 into bf16 hi/lo images ----------------
__global__ void pack_kernel(const float* __restrict__ vW1, const float* __restrict__ pW1) {
    if (blockIdx.x == 0 && blockIdx.y == 0 && threadIdx.x == 0) {
        g_vcount = 0; g_pcount = 0;
    }
    int head = blockIdx.y;
    const float* W = head ? pW1 : vW1;
    int q  = blockIdx.x * blockDim.x + threadIdx.x;  // 0..32767
    int n  = q >> 7;                                 // H row 0..255
    int kq = (q & 127) * 4;                          // k 0..508
    float4 f = *(const float4*)(W + (size_t)n * DIN + kq);

    uint16_t h0, h1, h2, h3, l0, l1, l2, l3;
    split_bf16(f.x, h0, l0); split_bf16(f.y, h1, l1);
    split_bf16(f.z, h2, l2); split_bf16(f.w, h3, l3);
    uint2 hv, lv;
    hv.x = (uint32_t)h0 | ((uint32_t)h1 << 16);
    hv.y = (uint32_t)h2 | ((uint32_t)h3 << 16);
    lv.x = (uint32_t)l0 | ((uint32_t)l1 << 16);
    lv.y = (uint32_t)l2 | ((uint32_t)l3 << 16);

    int chunk = kq >> 5;           // KC=32
    int kk = kq & 31;
    unsigned char* basep = g_wpack + (size_t)head * (NCHUNK * 32768) + (size_t)chunk * 32768;
    *(uint2*)(basep + (size_t)n * 64 + kk * 2)         = hv;   // hi
    *(uint2*)(basep + 16384 + (size_t)n * 64 + kk * 2) = lv;   // lo
}

// ---------------- kernel: classify + zero output + masks ----------------
__global__ void classify_kernel(const int* __restrict__ ids32,
                                float* __restrict__ out, int mask_mode) {
    __shared__ int sIs64;
    if (threadIdx.x < 32) {
        int v = ids32[2 * threadIdx.x + 1] | ids32[2 * threadIdx.x + 65] |
                ids32[2 * threadIdx.x + 129] | ids32[2 * threadIdx.x + 193];
        unsigned nz = __ballot_sync(0xffffffffu, v != 0);
        if (threadIdx.x == 0) sIs64 = (nz == 0);
    }
    __syncthreads();
    int t = blockIdx.x * blockDim.x + threadIdx.x;
    if (t >= TOKENS) return;
    int type = sIs64 ? ids32[2 * t] : ids32[t];
    bool vm = (type == 1);
    bool pm = (type == 2);

    float* row = out + (size_t)t * 6;
    #pragma unroll
    for (int o = 0; o < 6; o++) row[o] = 0.0f;

    if (mask_mode == 1) {
        out[TOKENS * 6 + t]          = vm ? 1.0f : 0.0f;
        out[TOKENS * 6 + TOKENS + t] = pm ? 1.0f : 0.0f;
    } else if (mask_mode == 2) {
        unsigned char* m = (unsigned char*)(out + TOKENS * 6);
        m[t]          = vm ? 1 : 0;
        m[TOKENS + t] = pm ? 1 : 0;
    }

    int lane = threadIdx.x & 31;
    unsigned vb = __ballot_sync(0xffffffffu, vm);
    if (vm) {
        int leader = __ffs(vb) - 1;
        int base = 0;
        if (lane == leader) base = atomicAdd(&g_vcount, __popc(vb));
        base = __shfl_sync(vb, base, leader);
        g_vidx[base + __popc(vb & ((1u << lane) - 1u))] = t;
    }
    unsigned pb = __ballot_sync(0xffffffffu, pm);
    if (pm) {
        int leader = __ffs(pb) - 1;
        int base = 0;
        if (lane == leader) base = atomicAdd(&g_pcount, __popc(pb));
        base = __shfl_sync(pb, base, leader);
        g_pidx[base + __popc(pb & ((1u << lane) - 1u))] = t;
    }
}

// ---------------- kernel: gathered bf16x3 HMMA MLP ----------------
__global__ __launch_bounds__(NT, 1)
void mlp_kernel(const float* __restrict__ repr3,
                const float* __restrict__ vW2, const float* __restrict__ vB1, const float* __restrict__ vB2,
                const float* __restrict__ pW2, const float* __restrict__ pB1, const float* __restrict__ pB2,
                float* __restrict__ out)
{
    const int head  = blockIdx.z;
    const int count = head ? g_pcount : g_vcount;
    const int base  = blockIdx.x * BM;
    if (base >= count) return;

    extern __shared__ unsigned char smem[];
    const uint32_t sb = smem_u32(smem);
    const int tid  = threadIdx.x;
    const int wid  = tid >> 5;
    const int lane = tid & 31;
    const int wm = wid & 3;          // 4 M tiles of 32 rows
    const int wn = wid >> 2;         // 4 N tiles of 64 cols
    const int m0 = wm * 32;
    const int n0 = wn * 64;

    const int* list  = head ? g_pidx : g_vidx;
    const float* W2p = head ? pW2 : vW2;
    const float* B1p = head ? pB1 : vB1;
    const float* B2p = head ? pB2 : vB2;
    const int odim   = head ? 2 : 6;
    const unsigned char* wsrc = g_wpack + (size_t)head * (NCHUNK * 32768);

    int*   sTok = (int*)(smem + TOK_OFF);
    float* sW2  = (float*)(smem + W2_OFF);
    float* sB1  = (float*)(smem + B1_OFF);
    float* sB2  = (float*)(smem + B2_OFF);
    float* sRed = (float*)(smem + RED_OFF);

    // ---- prologue ----
    if (tid < BM) {
        int m = base + tid;
        sTok[tid] = (m < count) ? list[m] : list[0];
    }
    for (int i = tid; i < 6 * HDIM; i += NT) sW2[i] = (i < odim * HDIM) ? W2p[i] : 0.0f;
    if (tid < HDIM) sB1[tid] = B1p[tid];
    if (tid < odim) sB2[tid] = B2p[tid];
    __syncthreads();

    // ---- per-thread load mappings ----
    // A: 128 rows x 32 k fp32 per chunk = 1024 float4; 2 per thread
    const int arow0 = tid >> 3;                // 0..63
    const int arow1 = arow0 + 64;              // 64..127
    const int akq   = (tid & 7) * 4;           // fp32 k offset within chunk
    const float* aSrc0 = repr3 + (size_t)sTok[arow0] * DIN + akq;
    const float* aSrc1 = repr3 + (size_t)sTok[arow1] * DIN + akq;
    const uint32_t aDst0 = (uint32_t)arow0 * ROWB + (uint32_t)akq * 2;
    const uint32_t aDst1 = (uint32_t)arow1 * ROWB + (uint32_t)akq * 2;

    // B: 32 KB per chunk = 2048 x 16B; 4 per thread
    uint32_t bSrcOff[4], bDstOff[4];
    #pragma unroll
    for (int i = 0; i < 4; i++) {
        int idx = tid + i * NT;                // 0..2047
        int split = idx >> 10;
        int sub = idx & 1023;
        int row = sub >> 2;
        int c16 = sub & 3;
        bSrcOff[i] = (uint32_t)split * 16384u + (uint32_t)row * 64u + (uint32_t)c16 * 16u;
        bDstOff[i] = (uint32_t)split * B_SPLIT + (uint32_t)row * ROWB + (uint32_t)c16 * 16u;
    }

    float c[2][8][4];
    #pragma unroll
    for (int mi = 0; mi < 2; mi++)
        #pragma unroll
        for (int ni = 0; ni < 8; ni++)
            #pragma unroll
            for (int j = 0; j < 4; j++) c[mi][ni][j] = 0.0f;

    // ---- ldmatrix address precompute (per stage handled by adding stage offset) ----
    const uint32_t aLdOff = (uint32_t)(((lane >> 3) & 1) * 8 + (lane & 7)) * ROWB + (uint32_t)(lane >> 4) * 16;
    const uint32_t bLdOff = (uint32_t)(((lane >> 4) & 1) * 8 + (lane & 7)) * ROWB + (uint32_t)((lane >> 3) & 1) * 16;

    // ---- chunk 0 loads ----
    {
        #pragma unroll
        for (int i = 0; i < 4; i++)
            cp_async16(sb + B_OFF + bDstOff[i], wsrc + bSrcOff[i]);
        CP_COMMIT();
        float4 f0 = *(const float4*)(aSrc0);
        float4 f1 = *(const float4*)(aSrc1);
        uint16_t h[4], l[4];
        unsigned char* aP = smem + A_OFF;
        split_bf16(f0.x, h[0], l[0]); split_bf16(f0.y, h[1], l[1]);
        split_bf16(f0.z, h[2], l[2]); split_bf16(f0.w, h[3], l[3]);
        *(uint2*)(aP + aDst0) = make_uint2((uint32_t)h[0] | ((uint32_t)h[1] << 16),
                                           (uint32_t)h[2] | ((uint32_t)h[3] << 16));
        *(uint2*)(aP + A_SPLIT + aDst0) = make_uint2((uint32_t)l[0] | ((uint32_t)l[1] << 16),
                                                     (uint32_t)l[2] | ((uint32_t)l[3] << 16));
        split_bf16(f1.x, h[0], l[0]); split_bf16(f1.y, h[1], l[1]);
        split_bf16(f1.z, h[2], l[2]); split_bf16(f1.w, h[3], l[3]);
        *(uint2*)(aP + aDst1) = make_uint2((uint32_t)h[0] | ((uint32_t)h[1] << 16),
                                           (uint32_t)h[2] | ((uint32_t)h[3] << 16));
        *(uint2*)(aP + A_SPLIT + aDst1) = make_uint2((uint32_t)l[0] | ((uint32_t)l[1] << 16),
                                                     (uint32_t)l[2] | ((uint32_t)l[3] << 16));
        CP_WAIT0();
        __syncthreads();
    }

    // ---- main K loop ----
    for (int ch = 0; ch < NCHUNK; ch++) {
        const int s  = ch & 1;
        const int ns = s ^ 1;
        float4 f0, f1;
        const bool more = (ch + 1 < NCHUNK);
        if (more) {
            #pragma unroll
            for (int i = 0; i < 4; i++)
                cp_async16(sb + B_OFF + ns * B_STAGE + bDstOff[i],
                           wsrc + (size_t)(ch + 1) * 32768 + bSrcOff[i]);
            CP_COMMIT();
            f0 = *(const float4*)(aSrc0 + (ch + 1) * KC);
            f1 = *(const float4*)(aSrc1 + (ch + 1) * KC);
        }

        // compute on stage s
        const uint32_t aB = sb + A_OFF + s * A_STAGE;
        const uint32_t bB = sb + B_OFF + s * B_STAGE;
        #pragma unroll
        for (int ks = 0; ks < 2; ks++) {
            uint32_t ah[2][4], al[2][4];
            #pragma unroll
            for (int mi = 0; mi < 2; mi++) {
                uint32_t off = (uint32_t)(m0 + mi * 16) * ROWB + (uint32_t)ks * 32 + aLdOff;
                ldm4(ah[mi], aB + off);
                ldm4(al[mi], aB + A_SPLIT + off);
            }
            #pragma unroll
            for (int np = 0; np < 4; np++) {
                uint32_t off = (uint32_t)(n0 + np * 16) * ROWB + (uint32_t)ks * 32 + bLdOff;
                uint32_t bh[4], bl[4];
                ldm4(bh, bB + off);
                ldm4(bl, bB + B_SPLIT + off);
                #pragma unroll
                for (int mi = 0; mi < 2; mi++) {
                    mma16816(c[mi][2 * np],     ah[mi], bh[0], bh[1]);
                    mma16816(c[mi][2 * np],     ah[mi], bl[0], bl[1]);
                    mma16816(c[mi][2 * np],     al[mi], bh[0], bh[1]);
                    mma16816(c[mi][2 * np + 1], ah[mi], bh[2], bh[3]);
                    mma16816(c[mi][2 * np + 1], ah[mi], bl[2], bl[3]);
                    mma16816(c[mi][2 * np + 1], al[mi], bh[2], bh[3]);
                }
            }
        }

        if (more) {
            uint16_t h[4], l[4];
            unsigned char* aP = smem + A_OFF + ns * A_STAGE;
            split_bf16(f0.x, h[0], l[0]); split_bf16(f0.y, h[1], l[1]);
            split_bf16(f0.z, h[2], l[2]); split_bf16(f0.w, h[3], l[3]);
            *(uint2*)(aP + aDst0) = make_uint2((uint32_t)h[0] | ((uint32_t)h[1] << 16),
                                               (uint32_t)h[2] | ((uint32_t)h[3] << 16));
            *(uint2*)(aP + A_SPLIT + aDst0) = make_uint2((uint32_t)l[0] | ((uint32_t)l[1] << 16),
                                                         (uint32_t)l[2] | ((uint32_t)l[3] << 16));
            split_bf16(f1.x, h[0], l[0]); split_bf16(f1.y, h[1], l[1]);
            split_bf16(f1.z, h[2], l[2]); split_bf16(f1.w, h[3], l[3]);
            *(uint2*)(aP + aDst1) = make_uint2((uint32_t)h[0] | ((uint32_t)h[1] << 16),
                                               (uint32_t)h[2] | ((uint32_t)h[3] << 16));
            *(uint2*)(aP + A_SPLIT + aDst1) = make_uint2((uint32_t)l[0] | ((uint32_t)l[1] << 16),
                                                         (uint32_t)l[2] | ((uint32_t)l[3] << 16));
            CP_WAIT0();
        }
        __syncthreads();
    }

    // ---- epilogue: bias + exact GELU + 256->{6,2} layer ----
    #pragma unroll
    for (int mi = 0; mi < 2; mi++) {
        #pragma unroll
        for (int half = 0; half < 2; half++) {
            float a6[6] = {0.f, 0.f, 0.f, 0.f, 0.f, 0.f};
            #pragma unroll
            for (int ni = 0; ni < 8; ni++) {
                #pragma unroll
                for (int e = 0; e < 2; e++) {
                    int col = n0 + ni * 8 + (lane & 3) * 2 + e;
                    float x = c[mi][ni][half * 2 + e] + sB1[col];
                    float hgl = 0.5f * x * (1.0f + erff(x * 0.70710678118654752f));
                    #pragma unroll
                    for (int o = 0; o < 6; o++)
                        a6[o] = fmaf(hgl, sW2[o * HDIM + col], a6[o]);
                }
            }
            #pragma unroll
            for (int o = 0; o < 6; o++) {
                a6[o] += __shfl_xor_sync(0xffffffffu, a6[o], 1);
                a6[o] += __shfl_xor_sync(0xffffffffu, a6[o], 2);
            }
            if ((lane & 3) == 0) {
                int row = m0 + mi * 16 + half * 8 + (lane >> 2);
                #pragma unroll
                for (int o = 0; o < 6; o++)
                    sRed[(wn * BM + row) * 6 + o] = a6[o];
            }
        }
    }
    __syncthreads();

    if (tid < BM && base + tid < count) {
        float* orow = out + (size_t)sTok[tid] * 6;
        #pragma unroll
        for (int o = 0; o < 6; o++) {
            if (o < odim) {
                float v = sRed[(0 * BM + tid) * 6 + o] + sRed[(1 * BM + tid) * 6 + o]
                        + sRed[(2 * BM + tid) * 6 + o] + sRed[(3 * BM + tid) * 6 + o]
                        + sB2[o];
                orow[o] = v;
            }
        }
    }
}

// ---------------- launch ----------------
extern "C" void kernel_launch(void* const* d_in, const int* in_sizes, int n_in,
                              void* d_out, int out_size) {
    const float* repr3 = (const float*)d_in[0];
    const int*   ids   = (const int*)d_in[1];
    const float* vW1 = (const float*)d_in[2];
    const float* vb1 = (const float*)d_in[3];
    const float* vW2 = (const float*)d_in[4];
    const float* vb2 = (const float*)d_in[5];
    const float* pW1 = (const float*)d_in[6];
    const float* pb1 = (const float*)d_in[7];
    const float* pW2 = (const float*)d_in[8];
    const float* pb2 = (const float*)d_in[9];
    float* out = (float*)d_out;

    int mask_mode = 0;
    if (out_size >= TOKENS * 6 + 2 * TOKENS)      mask_mode = 1;
    else if (out_size >= TOKENS * 6 + TOKENS / 2) mask_mode = 2;

    cudaFuncSetAttribute(mlp_kernel, cudaFuncAttributeMaxDynamicSharedMemorySize, SMEM_TOTAL);

    pack_kernel<<<dim3(128, 2), 256>>>(vW1, pW1);
    classify_kernel<<<TOKENS / 256, 256>>>(ids, out, mask_mode);

    dim3 grid(TOKENS / BM, 1, 2);   // early-exit past each head's count
    mlp_kernel<<<grid, NT, SMEM_TOTAL>>>(repr3, vW2, vb1, vb2, pW2, pb1, pb2, out);
}

// round 4
// speedup vs baseline: 2.8959x; 1.2489x over previous
#include <cuda_runtime.h>
#include <cuda_fp16.h>
#include <math.h>
#include <stdint.h>

#define TOKENS 65536
#define DIN 512
#define HDIM 256
#define BM 64             // tokens per CTA tile
#define KC 32             // fp32 K elements per chunk
#define NCHUNK 16         // 512/32
#define NT 256            // threads per CTA
#define ROWB 80           // padded smem row bytes (32 fp16 = 64B + 16B pad)

// ---- dynamic SMEM layout (bytes) ----
#define A_OFF     0
#define A_SPLIT   5120    // 64 rows * 80
#define A_STAGE   10240   // hi + lo
#define B_OFF     20480   // 2 stages x 20480 (256 rows * 80, single fp16)
#define B_STAGE   20480
#define TOK_OFF   61440   // int[64]
#define W2_OFF    61696   // float[6*256]
#define B1_OFF    67840   // float[256]
#define B2_OFF    68864   // float[8]
#define RED_OFF   68896   // float[4][64][6]
#define SMEM_TOTAL 75040

// ---------------- device globals (allocation-free scratch) ----------------
__device__ int g_vcount, g_pcount;
__device__ int g_vidx[TOKENS];
__device__ int g_pidx[TOKENS];
// prepacked W1 fp16, both heads: [head][chunk][256 rows x 64B]
__device__ __align__(16) unsigned char g_wpack[2 * NCHUNK * 16384];

// ---------------- PTX helpers ----------------
__device__ __forceinline__ uint32_t smem_u32(const void* p) {
    uint32_t a;
    asm("{ .reg .u64 t; cvta.to.shared.u64 t, %1; cvt.u32.u64 %0, t; }" : "=r"(a) : "l"(p));
    return a;
}
__device__ __forceinline__ void cp_async16(uint32_t dst, const void* src) {
    asm volatile("cp.async.ca.shared.global [%0], [%1], 16;" :: "r"(dst), "l"(src) : "memory");
}
#define CP_COMMIT() asm volatile("cp.async.commit_group;" ::: "memory")
#define CP_WAIT0()  asm volatile("cp.async.wait_group 0;" ::: "memory")

__device__ __forceinline__ void ldm4(uint32_t (&r)[4], uint32_t addr) {
    asm volatile("ldmatrix.sync.aligned.m8n8.x4.shared.b16 {%0,%1,%2,%3}, [%4];"
        : "=r"(r[0]), "=r"(r[1]), "=r"(r[2]), "=r"(r[3]) : "r"(addr));
}
__device__ __forceinline__ void mma16816(float (&d)[4], const uint32_t (&a)[4],
                                         uint32_t b0, uint32_t b1) {
    asm volatile(
        "mma.sync.aligned.m16n8k16.row.col.f32.f16.f16.f32 "
        "{%0,%1,%2,%3},{%4,%5,%6,%7},{%8,%9},{%0,%1,%2,%3};"
        : "+f"(d[0]), "+f"(d[1]), "+f"(d[2]), "+f"(d[3])
        : "r"(a[0]), "r"(a[1]), "r"(a[2]), "r"(a[3]), "r"(b0), "r"(b1));
}

__device__ __forceinline__ void split_f16(float x, uint16_t& h, uint16_t& l) {
    __half hb = __float2half_rn(x);
    __half lb = __float2half_rn(x - __half2float(hb));
    h = __half_as_ushort(hb);
    l = __half_as_ushort(lb);
}

// ---------------- kernel: prepack W1 into single-fp16 image ----------------
__global__ void pack_kernel(const float* __restrict__ vW1, const float* __restrict__ pW1) {
    if (blockIdx.x == 0 && blockIdx.y == 0 && threadIdx.x == 0) {
        g_vcount = 0; g_pcount = 0;
    }
    int head = blockIdx.y;
    const float* W = head ? pW1 : vW1;
    int q  = blockIdx.x * blockDim.x + threadIdx.x;  // 0..32767
    int n  = q >> 7;                                 // H row 0..255
    int kq = (q & 127) * 4;                          // k 0..508
    float4 f = *(const float4*)(W + (size_t)n * DIN + kq);

    uint16_t h0 = __half_as_ushort(__float2half_rn(f.x));
    uint16_t h1 = __half_as_ushort(__float2half_rn(f.y));
    uint16_t h2 = __half_as_ushort(__float2half_rn(f.z));
    uint16_t h3 = __half_as_ushort(__float2half_rn(f.w));
    uint2 hv;
    hv.x = (uint32_t)h0 | ((uint32_t)h1 << 16);
    hv.y = (uint32_t)h2 | ((uint32_t)h3 << 16);

    int chunk = kq >> 5;           // KC=32
    int kk = kq & 31;
    unsigned char* basep = g_wpack + (size_t)head * (NCHUNK * 16384) + (size_t)chunk * 16384;
    *(uint2*)(basep + (size_t)n * 64 + kk * 2) = hv;
}

// ---------------- kernel: classify + zero output + masks ----------------
__global__ void classify_kernel(const int* __restrict__ ids32,
                                float* __restrict__ out, int mask_mode) {
    __shared__ int sIs64;
    if (threadIdx.x < 32) {
        int v = ids32[2 * threadIdx.x + 1] | ids32[2 * threadIdx.x + 65] |
                ids32[2 * threadIdx.x + 129] | ids32[2 * threadIdx.x + 193];
        unsigned nz = __ballot_sync(0xffffffffu, v != 0);
        if (threadIdx.x == 0) sIs64 = (nz == 0);
    }
    __syncthreads();
    int t = blockIdx.x * blockDim.x + threadIdx.x;
    if (t >= TOKENS) return;
    int type = sIs64 ? ids32[2 * t] : ids32[t];
    bool vm = (type == 1);
    bool pm = (type == 2);

    float* row = out + (size_t)t * 6;
    #pragma unroll
    for (int o = 0; o < 6; o++) row[o] = 0.0f;

    if (mask_mode == 1) {
        out[TOKENS * 6 + t]          = vm ? 1.0f : 0.0f;
        out[TOKENS * 6 + TOKENS + t] = pm ? 1.0f : 0.0f;
    } else if (mask_mode == 2) {
        unsigned char* m = (unsigned char*)(out + TOKENS * 6);
        m[t]          = vm ? 1 : 0;
        m[TOKENS + t] = pm ? 1 : 0;
    }

    int lane = threadIdx.x & 31;
    unsigned vb = __ballot_sync(0xffffffffu, vm);
    if (vm) {
        int leader = __ffs(vb) - 1;
        int base = 0;
        if (lane == leader) base = atomicAdd(&g_vcount, __popc(vb));
        base = __shfl_sync(vb, base, leader);
        g_vidx[base + __popc(vb & ((1u << lane) - 1u))] = t;
    }
    unsigned pb = __ballot_sync(0xffffffffu, pm);
    if (pm) {
        int leader = __ffs(pb) - 1;
        int base = 0;
        if (lane == leader) base = atomicAdd(&g_pcount, __popc(pb));
        base = __shfl_sync(pb, base, leader);
        g_pidx[base + __popc(pb & ((1u << lane) - 1u))] = t;
    }
}

// ---------------- kernel: gathered fp16 2-term HMMA MLP ----------------
__global__ __launch_bounds__(NT, 2)
void mlp_kernel(const float* __restrict__ repr3,
                const float* __restrict__ vW2, const float* __restrict__ vB1, const float* __restrict__ vB2,
                const float* __restrict__ pW2, const float* __restrict__ pB1, const float* __restrict__ pB2,
                float* __restrict__ out)
{
    const int head  = blockIdx.z;
    const int count = head ? g_pcount : g_vcount;
    const int base  = blockIdx.x * BM;
    if (base >= count) return;

    extern __shared__ unsigned char smem[];
    const uint32_t sb = smem_u32(smem);
    const int tid  = threadIdx.x;
    const int wid  = tid >> 5;
    const int lane = tid & 31;
    const int wm = wid & 1;          // 2 M tiles of 32 rows
    const int wn = wid >> 1;         // 4 N tiles of 64 cols
    const int m0 = wm * 32;
    const int n0 = wn * 64;

    const int* list  = head ? g_pidx : g_vidx;
    const float* W2p = head ? pW2 : vW2;
    const float* B1p = head ? pB1 : vB1;
    const float* B2p = head ? pB2 : vB2;
    const int odim   = head ? 2 : 6;
    const unsigned char* wsrc = g_wpack + (size_t)head * (NCHUNK * 16384);

    int*   sTok = (int*)(smem + TOK_OFF);
    float* sW2  = (float*)(smem + W2_OFF);
    float* sB1  = (float*)(smem + B1_OFF);
    float* sB2  = (float*)(smem + B2_OFF);
    float* sRed = (float*)(smem + RED_OFF);

    // ---- prologue ----
    if (tid < BM) {
        int m = base + tid;
        sTok[tid] = (m < count) ? list[m] : list[0];
    }
    for (int i = tid; i < 6 * HDIM; i += NT) sW2[i] = (i < odim * HDIM) ? W2p[i] : 0.0f;
    if (tid < HDIM) sB1[tid] = B1p[tid];
    if (tid < odim) sB2[tid] = B2p[tid];
    __syncthreads();

    // ---- per-thread load mappings ----
    // A: 64 rows x 32 fp32 per chunk = 512 float4; 2 consecutive per thread
    const int arow = tid >> 2;                 // 0..63
    const int akq  = (tid & 3) * 8;            // fp32 k offset within chunk
    const float* aSrc = repr3 + (size_t)sTok[arow] * DIN + akq;
    const uint32_t aDst = (uint32_t)arow * ROWB + (uint32_t)akq * 2;

    // B: 16 KB per chunk = 1024 x 16B; 4 per thread
    uint32_t bSrcOff[4], bDstOff[4];
    #pragma unroll
    for (int i = 0; i < 4; i++) {
        int idx = tid + i * NT;                // 0..1023
        int row = idx >> 2;                    // 0..255
        int c16 = idx & 3;
        bSrcOff[i] = (uint32_t)row * 64u + (uint32_t)c16 * 16u;
        bDstOff[i] = (uint32_t)row * ROWB + (uint32_t)c16 * 16u;
    }

    float c[2][8][4];
    #pragma unroll
    for (int mi = 0; mi < 2; mi++)
        #pragma unroll
        for (int ni = 0; ni < 8; ni++)
            #pragma unroll
            for (int j = 0; j < 4; j++) c[mi][ni][j] = 0.0f;

    const uint32_t aLdOff = (uint32_t)(((lane >> 3) & 1) * 8 + (lane & 7)) * ROWB + (uint32_t)(lane >> 4) * 16;
    const uint32_t bLdOff = (uint32_t)(((lane >> 4) & 1) * 8 + (lane & 7)) * ROWB + (uint32_t)((lane >> 3) & 1) * 16;

    // ---- A register->smem split helper ----
    auto storeA = [&](unsigned char* aP, float4 f0, float4 f1) {
        uint16_t h[8], l[8];
        split_f16(f0.x, h[0], l[0]); split_f16(f0.y, h[1], l[1]);
        split_f16(f0.z, h[2], l[2]); split_f16(f0.w, h[3], l[3]);
        split_f16(f1.x, h[4], l[4]); split_f16(f1.y, h[5], l[5]);
        split_f16(f1.z, h[6], l[6]); split_f16(f1.w, h[7], l[7]);
        uint4 hv, lv;
        hv.x = (uint32_t)h[0] | ((uint32_t)h[1] << 16);
        hv.y = (uint32_t)h[2] | ((uint32_t)h[3] << 16);
        hv.z = (uint32_t)h[4] | ((uint32_t)h[5] << 16);
        hv.w = (uint32_t)h[6] | ((uint32_t)h[7] << 16);
        lv.x = (uint32_t)l[0] | ((uint32_t)l[1] << 16);
        lv.y = (uint32_t)l[2] | ((uint32_t)l[3] << 16);
        lv.z = (uint32_t)l[4] | ((uint32_t)l[5] << 16);
        lv.w = (uint32_t)l[6] | ((uint32_t)l[7] << 16);
        *(uint4*)(aP + aDst)           = hv;
        *(uint4*)(aP + A_SPLIT + aDst) = lv;
    };

    // ---- chunk 0 loads ----
    {
        #pragma unroll
        for (int i = 0; i < 4; i++)
            cp_async16(sb + B_OFF + bDstOff[i], wsrc + bSrcOff[i]);
        CP_COMMIT();
        float4 f0 = *(const float4*)(aSrc);
        float4 f1 = *(const float4*)(aSrc + 4);
        storeA(smem + A_OFF, f0, f1);
        CP_WAIT0();
        __syncthreads();
    }

    // ---- main K loop ----
    for (int ch = 0; ch < NCHUNK; ch++) {
        const int s  = ch & 1;
        const int ns = s ^ 1;
        float4 f0, f1;
        const bool more = (ch + 1 < NCHUNK);
        if (more) {
            #pragma unroll
            for (int i = 0; i < 4; i++)
                cp_async16(sb + B_OFF + ns * B_STAGE + bDstOff[i],
                           wsrc + (size_t)(ch + 1) * 16384 + bSrcOff[i]);
            CP_COMMIT();
            f0 = *(const float4*)(aSrc + (ch + 1) * KC);
            f1 = *(const float4*)(aSrc + (ch + 1) * KC + 4);
        }

        const uint32_t aB = sb + A_OFF + s * A_STAGE;
        const uint32_t bB = sb + B_OFF + s * B_STAGE;
        #pragma unroll
        for (int ks = 0; ks < 2; ks++) {
            uint32_t ah[2][4], al[2][4];
            #pragma unroll
            for (int mi = 0; mi < 2; mi++) {
                uint32_t off = (uint32_t)(m0 + mi * 16) * ROWB + (uint32_t)ks * 32 + aLdOff;
                ldm4(ah[mi], aB + off);
                ldm4(al[mi], aB + A_SPLIT + off);
            }
            #pragma unroll
            for (int np = 0; np < 4; np++) {
                uint32_t off = (uint32_t)(n0 + np * 16) * ROWB + (uint32_t)ks * 32 + bLdOff;
                uint32_t b[4];
                ldm4(b, bB + off);
                #pragma unroll
                for (int mi = 0; mi < 2; mi++) {
                    mma16816(c[mi][2 * np],     ah[mi], b[0], b[1]);
                    mma16816(c[mi][2 * np],     al[mi], b[0], b[1]);
                    mma16816(c[mi][2 * np + 1], ah[mi], b[2], b[3]);
                    mma16816(c[mi][2 * np + 1], al[mi], b[2], b[3]);
                }
            }
        }

        if (more) {
            storeA(smem + A_OFF + ns * A_STAGE, f0, f1);
            CP_WAIT0();
        }
        __syncthreads();
    }

    // ---- epilogue: bias + exact GELU + 256->{6,2} layer ----
    #pragma unroll
    for (int mi = 0; mi < 2; mi++) {
        #pragma unroll
        for (int half = 0; half < 2; half++) {
            float a6[6] = {0.f, 0.f, 0.f, 0.f, 0.f, 0.f};
            #pragma unroll
            for (int ni = 0; ni < 8; ni++) {
                #pragma unroll
                for (int e = 0; e < 2; e++) {
                    int col = n0 + ni * 8 + (lane & 3) * 2 + e;
                    float x = c[mi][ni][half * 2 + e] + sB1[col];
                    float hgl = 0.5f * x * (1.0f + erff(x * 0.70710678118654752f));
                    #pragma unroll
                    for (int o = 0; o < 6; o++)
                        a6[o] = fmaf(hgl, sW2[o * HDIM + col], a6[o]);
                }
            }
            #pragma unroll
            for (int o = 0; o < 6; o++) {
                a6[o] += __shfl_xor_sync(0xffffffffu, a6[o], 1);
                a6[o] += __shfl_xor_sync(0xffffffffu, a6[o], 2);
            }
            if ((lane & 3) == 0) {
                int row = m0 + mi * 16 + half * 8 + (lane >> 2);
                #pragma unroll
                for (int o = 0; o < 6; o++)
                    sRed[(wn * BM + row) * 6 + o] = a6[o];
            }
        }
    }
    __syncthreads();

    if (tid < BM && base + tid < count) {
        float* orow = out + (size_t)sTok[tid] * 6;
        #pragma unroll
        for (int o = 0; o < 6; o++) {
            if (o < odim) {
                float v = sRed[(0 * BM + tid) * 6 + o] + sRed[(1 * BM + tid) * 6 + o]
                        + sRed[(2 * BM + tid) * 6 + o] + sRed[(3 * BM + tid) * 6 + o]
                        + sB2[o];
                orow[o] = v;
            }
        }
    }
}

// ---------------- launch ----------------
extern "C" void kernel_launch(void* const* d_in, const int* in_sizes, int n_in,
                              void* d_out, int out_size) {
    const float* repr3 = (const float*)d_in[0];
    const int*   ids   = (const int*)d_in[1];
    const float* vW1 = (const float*)d_in[2];
    const float* vb1 = (const float*)d_in[3];
    const float* vW2 = (const float*)d_in[4];
    const float* vb2 = (const float*)d_in[5];
    const float* pW1 = (const float*)d_in[6];
    const float* pb1 = (const float*)d_in[7];
    const float* pW2 = (const float*)d_in[8];
    const float* pb2 = (const float*)d_in[9];
    float* out = (float*)d_out;

    int mask_mode = 0;
    if (out_size >= TOKENS * 6 + 2 * TOKENS)      mask_mode = 1;
    else if (out_size >= TOKENS * 6 + TOKENS / 2) mask_mode = 2;

    cudaFuncSetAttribute(mlp_kernel, cudaFuncAttributeMaxDynamicSharedMemorySize, SMEM_TOTAL);

    pack_kernel<<<dim3(128, 2), 256>>>(vW1, pW1);
    classify_kernel<<<TOKENS / 256, 256>>>(ids, out, mask_mode);

    dim3 grid(TOKENS / BM, 1, 2);   // early-exit past each head's count
    mlp_kernel<<<grid, NT, SMEM_TOTAL>>>(repr3, vW2, vb1, vb2, pW2, pb1, pb2, out);
}

// round 5
// speedup vs baseline: 3.5989x; 1.2428x over previous
#include <cuda_runtime.h>
#include <cuda_fp16.h>
#include <math.h>
#include <stdint.h>

#define TOKENS 65536
#define DIN 512
#define HDIM 256
#define BM 64             // tokens per CTA tile
#define KC 32             // fp32 K elements per chunk
#define NCHUNK 16         // 512/32
#define NT 256            // threads per CTA
#define ROWB 80           // padded smem row bytes (32 fp16 = 64B + 16B pad)
#define GRID 304          // 2 CTAs/SM x 152 SMs, persistent

// ---- dynamic SMEM layout (bytes) ----
#define A_OFF     0       // 2 stages x 5120 (64 rows * 80, single fp16)
#define A_STAGE   5120
#define B_OFF     10240   // 2 stages x 20480 (256 rows * 80, single fp16)
#define B_STAGE   20480
#define TOK_OFF   51200   // int[64]
#define W2_OFF    51456   // float[6*256]
#define B1_OFF    57600   // float[256]
#define B2_OFF    58624   // float[8]
#define RED_OFF   58656   // float[4][64][6]
#define TILE_OFF  64800   // int
#define SMEM_TOTAL 64832

// ---------------- device globals (allocation-free scratch) ----------------
__device__ int g_vcount, g_pcount, g_ticket;
__device__ int g_vidx[TOKENS];
__device__ int g_pidx[TOKENS];
// prepacked W1 fp16, both heads: [head][chunk][256 rows x 64B]
__device__ __align__(16) unsigned char g_wpack[2 * NCHUNK * 16384];

// ---------------- PTX helpers ----------------
__device__ __forceinline__ uint32_t smem_u32(const void* p) {
    uint32_t a;
    asm("{ .reg .u64 t; cvta.to.shared.u64 t, %1; cvt.u32.u64 %0, t; }" : "=r"(a) : "l"(p));
    return a;
}
__device__ __forceinline__ void cp_async16(uint32_t dst, const void* src) {
    asm volatile("cp.async.ca.shared.global [%0], [%1], 16;" :: "r"(dst), "l"(src) : "memory");
}
#define CP_COMMIT() asm volatile("cp.async.commit_group;" ::: "memory")
#define CP_WAIT0()  asm volatile("cp.async.wait_group 0;" ::: "memory")

__device__ __forceinline__ void ldm4(uint32_t (&r)[4], uint32_t addr) {
    asm volatile("ldmatrix.sync.aligned.m8n8.x4.shared.b16 {%0,%1,%2,%3}, [%4];"
        : "=r"(r[0]), "=r"(r[1]), "=r"(r[2]), "=r"(r[3]) : "r"(addr));
}
__device__ __forceinline__ void mma16816(float (&d)[4], const uint32_t (&a)[4],
                                         uint32_t b0, uint32_t b1) {
    asm volatile(
        "mma.sync.aligned.m16n8k16.row.col.f32.f16.f16.f32 "
        "{%0,%1,%2,%3},{%4,%5,%6,%7},{%8,%9},{%0,%1,%2,%3};"
        : "+f"(d[0]), "+f"(d[1]), "+f"(d[2]), "+f"(d[3])
        : "r"(a[0]), "r"(a[1]), "r"(a[2]), "r"(a[3]), "r"(b0), "r"(b1));
}

// ---------------- kernel: prepack W1 fp16 + reset counters ----------------
__global__ void pack_kernel(const float* __restrict__ vW1, const float* __restrict__ pW1) {
    if (blockIdx.x == 0 && blockIdx.y == 0 && threadIdx.x == 0) {
        g_vcount = 0; g_pcount = 0; g_ticket = 0;
    }
    int head = blockIdx.y;
    const float* W = head ? pW1 : vW1;
    int q  = blockIdx.x * blockDim.x + threadIdx.x;  // 0..32767
    int n  = q >> 7;                                 // H row 0..255
    int kq = (q & 127) * 4;                          // k 0..508
    float4 f = *(const float4*)(W + (size_t)n * DIN + kq);

    uint16_t h0 = __half_as_ushort(__float2half_rn(f.x));
    uint16_t h1 = __half_as_ushort(__float2half_rn(f.y));
    uint16_t h2 = __half_as_ushort(__float2half_rn(f.z));
    uint16_t h3 = __half_as_ushort(__float2half_rn(f.w));
    uint2 hv;
    hv.x = (uint32_t)h0 | ((uint32_t)h1 << 16);
    hv.y = (uint32_t)h2 | ((uint32_t)h3 << 16);

    int chunk = kq >> 5;           // KC=32
    int kk = kq & 31;
    unsigned char* basep = g_wpack + (size_t)head * (NCHUNK * 16384) + (size_t)chunk * 16384;
    *(uint2*)(basep + (size_t)n * 64 + kk * 2) = hv;
}

// ---------------- kernel: classify + zero output + masks ----------------
__global__ void classify_kernel(const int* __restrict__ ids32,
                                float* __restrict__ out, int mask_mode) {
    __shared__ int sIs64;
    if (threadIdx.x < 32) {
        int v = ids32[2 * threadIdx.x + 1] | ids32[2 * threadIdx.x + 65] |
                ids32[2 * threadIdx.x + 129] | ids32[2 * threadIdx.x + 193];
        unsigned nz = __ballot_sync(0xffffffffu, v != 0);
        if (threadIdx.x == 0) sIs64 = (nz == 0);
    }
    __syncthreads();
    int t = blockIdx.x * blockDim.x + threadIdx.x;
    if (t >= TOKENS) return;
    int type = sIs64 ? ids32[2 * t] : ids32[t];
    bool vm = (type == 1);
    bool pm = (type == 2);

    float* row = out + (size_t)t * 6;
    #pragma unroll
    for (int o = 0; o < 6; o++) row[o] = 0.0f;

    if (mask_mode == 1) {
        out[TOKENS * 6 + t]          = vm ? 1.0f : 0.0f;
        out[TOKENS * 6 + TOKENS + t] = pm ? 1.0f : 0.0f;
    } else if (mask_mode == 2) {
        unsigned char* m = (unsigned char*)(out + TOKENS * 6);
        m[t]          = vm ? 1 : 0;
        m[TOKENS + t] = pm ? 1 : 0;
    }

    int lane = threadIdx.x & 31;
    unsigned vb = __ballot_sync(0xffffffffu, vm);
    if (vm) {
        int leader = __ffs(vb) - 1;
        int base = 0;
        if (lane == leader) base = atomicAdd(&g_vcount, __popc(vb));
        base = __shfl_sync(vb, base, leader);
        g_vidx[base + __popc(vb & ((1u << lane) - 1u))] = t;
    }
    unsigned pb = __ballot_sync(0xffffffffu, pm);
    if (pm) {
        int leader = __ffs(pb) - 1;
        int base = 0;
        if (lane == leader) base = atomicAdd(&g_pcount, __popc(pb));
        base = __shfl_sync(pb, base, leader);
        g_pidx[base + __popc(pb & ((1u << lane) - 1u))] = t;
    }
}

// ---------------- kernel: persistent single-fp16 HMMA MLP ----------------
__global__ __launch_bounds__(NT, 2)
void mlp_kernel(const float* __restrict__ repr3,
                const float* __restrict__ vW2, const float* __restrict__ vB1, const float* __restrict__ vB2,
                const float* __restrict__ pW2, const float* __restrict__ pB1, const float* __restrict__ pB2,
                float* __restrict__ out)
{
    extern __shared__ unsigned char smem[];
    const uint32_t sb = smem_u32(smem);
    const int tid  = threadIdx.x;
    const int wid  = tid >> 5;
    const int lane = tid & 31;
    const int wm = wid & 1;          // 2 M tiles of 32 rows
    const int wn = wid >> 1;         // 4 N tiles of 64 cols
    const int m0 = wm * 32;
    const int n0 = wn * 64;

    int*   sTok  = (int*)(smem + TOK_OFF);
    float* sW2   = (float*)(smem + W2_OFF);
    float* sB1   = (float*)(smem + B1_OFF);
    float* sB2   = (float*)(smem + B2_OFF);
    float* sRed  = (float*)(smem + RED_OFF);
    int*   sTile = (int*)(smem + TILE_OFF);

    const int nv = g_vcount, np = g_pcount;
    const int nvt = (nv + BM - 1) / BM;
    const int npt = (np + BM - 1) / BM;
    const int ntiles = nvt + npt;

    // per-thread constant mappings
    const int arow = tid >> 2;                 // 0..63
    const int akq  = (tid & 3) * 8;            // fp32 k offset within chunk
    const uint32_t aDst = (uint32_t)arow * ROWB + (uint32_t)akq * 2;

    uint32_t bSrcOff[4], bDstOff[4];
    #pragma unroll
    for (int i = 0; i < 4; i++) {
        int idx = tid + i * NT;                // 0..1023
        int row = idx >> 2;
        int c16 = idx & 3;
        bSrcOff[i] = (uint32_t)row * 64u + (uint32_t)c16 * 16u;
        bDstOff[i] = (uint32_t)row * ROWB + (uint32_t)c16 * 16u;
    }

    const uint32_t aLdOff = (uint32_t)(((lane >> 3) & 1) * 8 + (lane & 7)) * ROWB + (uint32_t)(lane >> 4) * 16;
    const uint32_t bLdOff = (uint32_t)(((lane >> 4) & 1) * 8 + (lane & 7)) * ROWB + (uint32_t)((lane >> 3) & 1) * 16;

    auto storeA = [&](unsigned char* aP, float4 f0, float4 f1) {
        uint4 hv;
        hv.x = (uint32_t)__half_as_ushort(__float2half_rn(f0.x)) |
               ((uint32_t)__half_as_ushort(__float2half_rn(f0.y)) << 16);
        hv.y = (uint32_t)__half_as_ushort(__float2half_rn(f0.z)) |
               ((uint32_t)__half_as_ushort(__float2half_rn(f0.w)) << 16);
        hv.z = (uint32_t)__half_as_ushort(__float2half_rn(f1.x)) |
               ((uint32_t)__half_as_ushort(__float2half_rn(f1.y)) << 16);
        hv.w = (uint32_t)__half_as_ushort(__float2half_rn(f1.z)) |
               ((uint32_t)__half_as_ushort(__float2half_rn(f1.w)) << 16);
        *(uint4*)(aP + aDst) = hv;
    };

    for (;;) {
        __syncthreads();      // previous tile's smem fully consumed
        if (tid == 0) *sTile = atomicAdd(&g_ticket, 1);
        __syncthreads();
        const int tile = *sTile;
        if (tile >= ntiles) break;

        const int head  = (tile >= nvt);
        const int tIdx  = head ? (tile - nvt) : tile;
        const int count = head ? np : nv;
        const int base  = tIdx * BM;
        const int* list  = head ? g_pidx : g_vidx;
        const float* W2p = head ? pW2 : vW2;
        const float* B1p = head ? pB1 : vB1;
        const float* B2p = head ? pB2 : vB2;
        const int odim   = head ? 2 : 6;
        const unsigned char* wsrc = g_wpack + (size_t)head * (NCHUNK * 16384);

        // ---- tile prologue ----
        if (tid < BM) {
            int m = base + tid;
            sTok[tid] = (m < count) ? list[m] : list[0];
        }
        for (int i = tid; i < 6 * HDIM; i += NT) sW2[i] = (i < odim * HDIM) ? W2p[i] : 0.0f;
        if (tid < HDIM) sB1[tid] = B1p[tid];
        if (tid < odim) sB2[tid] = B2p[tid];
        __syncthreads();

        const float* aSrc = repr3 + (size_t)sTok[arow] * DIN + akq;

        float c[2][8][4];
        #pragma unroll
        for (int mi = 0; mi < 2; mi++)
            #pragma unroll
            for (int ni = 0; ni < 8; ni++)
                #pragma unroll
                for (int j = 0; j < 4; j++) c[mi][ni][j] = 0.0f;

        // ---- chunk 0 loads ----
        {
            #pragma unroll
            for (int i = 0; i < 4; i++)
                cp_async16(sb + B_OFF + bDstOff[i], wsrc + bSrcOff[i]);
            CP_COMMIT();
            float4 f0 = *(const float4*)(aSrc);
            float4 f1 = *(const float4*)(aSrc + 4);
            storeA(smem + A_OFF, f0, f1);
            CP_WAIT0();
            __syncthreads();
        }

        // ---- main K loop ----
        for (int ch = 0; ch < NCHUNK; ch++) {
            const int s  = ch & 1;
            const int ns = s ^ 1;
            float4 f0, f1;
            const bool more = (ch + 1 < NCHUNK);
            if (more) {
                #pragma unroll
                for (int i = 0; i < 4; i++)
                    cp_async16(sb + B_OFF + ns * B_STAGE + bDstOff[i],
                               wsrc + (size_t)(ch + 1) * 16384 + bSrcOff[i]);
                CP_COMMIT();
                f0 = *(const float4*)(aSrc + (ch + 1) * KC);
                f1 = *(const float4*)(aSrc + (ch + 1) * KC + 4);
            }

            const uint32_t aB = sb + A_OFF + s * A_STAGE;
            const uint32_t bB = sb + B_OFF + s * B_STAGE;
            #pragma unroll
            for (int ks = 0; ks < 2; ks++) {
                uint32_t ah[2][4];
                #pragma unroll
                for (int mi = 0; mi < 2; mi++) {
                    uint32_t off = (uint32_t)(m0 + mi * 16) * ROWB + (uint32_t)ks * 32 + aLdOff;
                    ldm4(ah[mi], aB + off);
                }
                #pragma unroll
                for (int npp = 0; npp < 4; npp++) {
                    uint32_t off = (uint32_t)(n0 + npp * 16) * ROWB + (uint32_t)ks * 32 + bLdOff;
                    uint32_t b[4];
                    ldm4(b, bB + off);
                    #pragma unroll
                    for (int mi = 0; mi < 2; mi++) {
                        mma16816(c[mi][2 * npp],     ah[mi], b[0], b[1]);
                        mma16816(c[mi][2 * npp + 1], ah[mi], b[2], b[3]);
                    }
                }
            }

            if (more) {
                storeA(smem + A_OFF + ns * A_STAGE, f0, f1);
                CP_WAIT0();
            }
            __syncthreads();
        }

        // ---- epilogue: bias + exact GELU + 256->{6,2} layer ----
        #pragma unroll
        for (int mi = 0; mi < 2; mi++) {
            #pragma unroll
            for (int half = 0; half < 2; half++) {
                float a6[6] = {0.f, 0.f, 0.f, 0.f, 0.f, 0.f};
                #pragma unroll
                for (int ni = 0; ni < 8; ni++) {
                    #pragma unroll
                    for (int e = 0; e < 2; e++) {
                        int col = n0 + ni * 8 + (lane & 3) * 2 + e;
                        float x = c[mi][ni][half * 2 + e] + sB1[col];
                        float hgl = 0.5f * x * (1.0f + erff(x * 0.70710678118654752f));
                        #pragma unroll
                        for (int o = 0; o < 6; o++)
                            a6[o] = fmaf(hgl, sW2[o * HDIM + col], a6[o]);
                    }
                }
                #pragma unroll
                for (int o = 0; o < 6; o++) {
                    a6[o] += __shfl_xor_sync(0xffffffffu, a6[o], 1);
                    a6[o] += __shfl_xor_sync(0xffffffffu, a6[o], 2);
                }
                if ((lane & 3) == 0) {
                    int row = m0 + mi * 16 + half * 8 + (lane >> 2);
                    #pragma unroll
                    for (int o = 0; o < 6; o++)
                        sRed[(wn * BM + row) * 6 + o] = a6[o];
                }
            }
        }
        __syncthreads();

        if (tid < BM && base + tid < count) {
            float* orow = out + (size_t)sTok[tid] * 6;
            #pragma unroll
            for (int o = 0; o < 6; o++) {
                if (o < odim) {
                    float v = sRed[(0 * BM + tid) * 6 + o] + sRed[(1 * BM + tid) * 6 + o]
                            + sRed[(2 * BM + tid) * 6 + o] + sRed[(3 * BM + tid) * 6 + o]
                            + sB2[o];
                    orow[o] = v;
                }
            }
        }
    }
}

// ---------------- launch ----------------
extern "C" void kernel_launch(void* const* d_in, const int* in_sizes, int n_in,
                              void* d_out, int out_size) {
    const float* repr3 = (const float*)d_in[0];
    const int*   ids   = (const int*)d_in[1];
    const float* vW1 = (const float*)d_in[2];
    const float* vb1 = (const float*)d_in[3];
    const float* vW2 = (const float*)d_in[4];
    const float* vb2 = (const float*)d_in[5];
    const float* pW1 = (const float*)d_in[6];
    const float* pb1 = (const float*)d_in[7];
    const float* pW2 = (const float*)d_in[8];
    const float* pb2 = (const float*)d_in[9];
    float* out = (float*)d_out;

    int mask_mode = 0;
    if (out_size >= TOKENS * 6 + 2 * TOKENS)      mask_mode = 1;
    else if (out_size >= TOKENS * 6 + TOKENS / 2) mask_mode = 2;

    cudaFuncSetAttribute(mlp_kernel, cudaFuncAttributeMaxDynamicSharedMemorySize, SMEM_TOTAL);

    pack_kernel<<<dim3(128, 2), 256>>>(vW1, pW1);
    classify_kernel<<<TOKENS / 256, 256>>>(ids, out, mask_mode);
    mlp_kernel<<<GRID, NT, SMEM_TOTAL>>>(repr3, vW2, vb1, vb2, pW2, pb1, pb2, out);
}